// round 7
// baseline (speedup 1.0000x reference)
#include <cuda_runtime.h>
#include <cuda_fp16.h>
#include <cstdint>

#define N_POINTS    2097152
#define CTA_THREADS 64
#define TILE_PTS    64                      // 2 warps x 32 rows
#define NTILES      (N_POINTS / TILE_PTS)   // 32768
#define NBLOCKS     (148 * 9)               // persistent

static __device__ __forceinline__ uint32_t pack_rn(float a, float b) {
    __half2 h = __floats2half2_rn(a, b);
    return *reinterpret_cast<uint32_t*>(&h);
}
static __device__ __forceinline__ __half2 u2h(uint32_t u) {
    return *reinterpret_cast<__half2*>(&u);
}
static __device__ __forceinline__ uint32_t h2u(__half2 h) {
    return *reinterpret_cast<uint32_t*>(&h);
}

// m16n8k16 fp16 MMA, fp32 accumulate in place
static __device__ __forceinline__ void mma16(float* d, const uint32_t* a,
                                             uint32_t b0, uint32_t b1)
{
    asm volatile(
        "mma.sync.aligned.m16n8k16.row.col.f32.f16.f16.f32 "
        "{%0,%1,%2,%3}, {%4,%5,%6,%7}, {%8,%9}, {%0,%1,%2,%3};"
        : "+f"(d[0]), "+f"(d[1]), "+f"(d[2]), "+f"(d[3])
        : "r"(a[0]), "r"(a[1]), "r"(a[2]), "r"(a[3]), "r"(b0), "r"(b1));
}

// m16n8k16 fp16 MMA, fp16 D, C = 0
static __device__ __forceinline__ void mma16_h(uint32_t* d, const uint32_t* a,
                                               uint32_t b0, uint32_t b1)
{
    asm volatile(
        "mma.sync.aligned.m16n8k16.row.col.f16.f16.f16.f16 "
        "{%0,%1}, {%2,%3,%4,%5}, {%6,%7}, {%8,%8};"
        : "=r"(d[0]), "=r"(d[1])
        : "r"(a[0]), "r"(a[1]), "r"(a[2]), "r"(a[3]), "r"(b0), "r"(b1), "r"(0u));
}

// issue cell gathers from ALREADY-RESIDENT coords (no load stall at the shfl)
static __device__ __forceinline__ void cell_gather(
    const float4* __restrict__ cellbase,
    float x, float y, float z, int g, int q, float4 f[4])
{
    const int ix = (int)rintf(fminf(fmaxf(x * 127.0f, 0.0f), 127.0f));
    const int iy = (int)rintf(fminf(fmaxf(y * 127.0f, 0.0f), 127.0f));
    const int iz = (int)rintf(fminf(fmaxf(z * 127.0f, 0.0f), 127.0f));
    const uint32_t ci = (uint32_t)(((ix << 7) + iy) << 7) + (uint32_t)iz;
#pragma unroll
    for (int r = 0; r < 4; r++) {
        const uint32_t cis = __shfl_sync(0xFFFFFFFFu, ci, r * 8 + g);
        f[r] = __ldg(cellbase + (size_t)cis * 4 + q);
    }
}

__global__ void __launch_bounds__(CTA_THREADS, 9)
occ_mlp_kernel(const float* __restrict__ points, const float* __restrict__ grid,
               const float* __restrict__ W1, const float* __restrict__ b1,
               const float* __restrict__ W2, const float* __restrict__ b2,
               const float* __restrict__ W3, const float* __restrict__ b3,
               float* __restrict__ out)
{
    // W2 B-fragments, uint4-packed: (nt*32+lane)*8 + kt*2 + h
    __shared__ __align__(16) uint32_t sW2q[8 * 32 * 8];   // 8 KB
    __shared__ __align__(16) float sB2[64], sW3s[64];
    __shared__ float sB3v;

    const int tid  = threadIdx.x;
    const int wid  = tid >> 5;
    const int lane = tid & 31;
    const int g    = lane >> 2;   // 0..7
    const int q    = lane & 3;    // 0..3

    // ---- W1 B-fragments + layer-1 bias (half2) register-resident ----
    uint2 w1f[8];
    uint32_t b1h[8];
#pragma unroll
    for (int nt = 0; nt < 8; nt++) {
        const float* Wn = W1 + (nt * 8 + g) * 16;
        w1f[nt].x = pack_rn(Wn[2 * q],     Wn[2 * q + 1]);
        w1f[nt].y = pack_rn(Wn[2 * q + 8], Wn[2 * q + 9]);
        const int c = nt * 8 + 2 * q;
        b1h[nt] = pack_rn(b1[c], b1[c + 1]);
    }
    // ---- stage W2 fragments into SMEM (uint4-friendly order) ----
    for (int i = tid; i < 8 * 32 * 8; i += CTA_THREADS) {
        int nt = i >> 8, ln = (i >> 3) & 31, j = i & 7;
        int kt = j >> 1, h = j & 1;
        int n = nt * 8 + (ln >> 2);
        int k = kt * 16 + 2 * (ln & 3) + 8 * h;
        sW2q[i] = pack_rn(W2[n * 64 + k], W2[n * 64 + k + 1]);
    }
    if (tid < 64) { sB2[tid] = b2[tid]; sW3s[tid] = W3[tid]; }
    if (tid == 0) sB3v = b3[0];
    __syncthreads();

    const float4* cellbase = (const float4*)grid;
    const __half2 zero2 = __floats2half2_rn(0.0f, 0.0f);
    const int lbase = wid * 32 + lane;

    // ---- prologue ----
    float4 fcur[4];
    float cx, cy, cz;          // coords for tile t+1 (resident 1 iter ahead)
    {
        const int t0 = blockIdx.x;
        if (t0 < NTILES) {
            const int p = t0 * TILE_PTS + lbase;
            const float x0 = __ldg(points + 3 * p);
            const float y0 = __ldg(points + 3 * p + 1);
            const float z0 = __ldg(points + 3 * p + 2);
            cell_gather(cellbase, x0, y0, z0, g, q, fcur);   // one cold stall only
        }
        const int t1 = t0 + gridDim.x;
        if (t1 < NTILES) {
            const int p = t1 * TILE_PTS + lbase;
            cx = __ldg(points + 3 * p);
            cy = __ldg(points + 3 * p + 1);
            cz = __ldg(points + 3 * p + 2);
        }
    }

    for (int tile = blockIdx.x; tile < NTILES; tile += gridDim.x) {
        const int p0 = tile * TILE_PTS + wid * 32;

        // ---- issue tile t+1 cell gathers (coords already resident) ----
        float4 fnext[4];
        const int ntile = tile + gridDim.x;
        if (ntile < NTILES)
            cell_gather(cellbase, cx, cy, cz, g, q, fnext);

        // ---- issue coords loads for tile t+2 (land by next iteration) ----
        const int nntile = tile + 2 * gridDim.x;
        if (nntile < NTILES) {
            const int p = nntile * TILE_PTS + lbase;
            cx = __ldg(points + 3 * p);
            cy = __ldg(points + 3 * p + 1);
            cz = __ldg(points + 3 * p + 2);
        }

        // ---- pack current cells to fp16 ----
        uint2 pc[4];
#pragma unroll
        for (int r = 0; r < 4; r++) {
            pc[r].x = pack_rn(fcur[r].x, fcur[r].y);
            pc[r].y = pack_rn(fcur[r].z, fcur[r].w);
        }

        // ---- shfl-transpose: build layer-1 A-fragments (intra-quad redistribution)
        // af[rt][0]: row rt*16+g    k=2q..2q+1   src lane 4g+(q>>1), half = q&1
        // af[rt][2]: row rt*16+g    k=2q+8..+9   src lane 4g+(q>>1)+2
        // af[rt][1/3]: same with row +8 (pc[2rt+1])
        uint32_t af[2][4];
        {
            const int srcA = (g << 2) + (q >> 1);
            const int srcB = srcA + 2;
            const bool hi = (q & 1);
#pragma unroll
            for (int rt = 0; rt < 2; rt++) {
                uint32_t xa0 = __shfl_sync(0xFFFFFFFFu, pc[2 * rt].x, srcA);
                uint32_t ya0 = __shfl_sync(0xFFFFFFFFu, pc[2 * rt].y, srcA);
                af[rt][0] = hi ? ya0 : xa0;
                uint32_t xa1 = __shfl_sync(0xFFFFFFFFu, pc[2 * rt + 1].x, srcA);
                uint32_t ya1 = __shfl_sync(0xFFFFFFFFu, pc[2 * rt + 1].y, srcA);
                af[rt][1] = hi ? ya1 : xa1;
                uint32_t xb0 = __shfl_sync(0xFFFFFFFFu, pc[2 * rt].x, srcB);
                uint32_t yb0 = __shfl_sync(0xFFFFFFFFu, pc[2 * rt].y, srcB);
                af[rt][2] = hi ? yb0 : xb0;
                uint32_t xb1 = __shfl_sync(0xFFFFFFFFu, pc[2 * rt + 1].x, srcB);
                uint32_t yb1 = __shfl_sync(0xFFFFFFFFu, pc[2 * rt + 1].y, srcB);
                af[rt][3] = hi ? yb1 : xb1;
            }
        }

        // ---- layer 1 (f16 D) -> layer-2 A-fragments in registers ----
        uint32_t a2r[2][4][4];   // [rt][kt][areg]
#pragma unroll
        for (int nt = 0; nt < 8; nt++) {
            const int kt = nt >> 1, hi2 = (nt & 1) * 2;
#pragma unroll
            for (int rt = 0; rt < 2; rt++) {
                uint32_t d[2];
                mma16_h(d, af[rt], w1f[nt].x, w1f[nt].y);
                a2r[rt][kt][hi2]     = h2u(__hmax2(__hadd2(u2h(d[0]), u2h(b1h[nt])), zero2));
                a2r[rt][kt][hi2 + 1] = h2u(__hmax2(__hadd2(u2h(d[1]), u2h(b1h[nt])), zero2));
            }
        }

        // ---- layer 2 + 3 fused ----
        float s[4] = {0.0f, 0.0f, 0.0f, 0.0f};   // rows g, g+8, g+16, g+24
#pragma unroll
        for (int nt = 0; nt < 8; nt++) {
            float acc[2][4];
            acc[0][0] = acc[0][1] = acc[0][2] = acc[0][3] = 0.0f;
            acc[1][0] = acc[1][1] = acc[1][2] = acc[1][3] = 0.0f;
            const uint4 B01 = *(const uint4*)(sW2q + (nt * 32 + lane) * 8);
            const uint4 B23 = *(const uint4*)(sW2q + (nt * 32 + lane) * 8 + 4);
            mma16(acc[0], a2r[0][0], B01.x, B01.y);
            mma16(acc[1], a2r[1][0], B01.x, B01.y);
            mma16(acc[0], a2r[0][1], B01.z, B01.w);
            mma16(acc[1], a2r[1][1], B01.z, B01.w);
            mma16(acc[0], a2r[0][2], B23.x, B23.y);
            mma16(acc[1], a2r[1][2], B23.x, B23.y);
            mma16(acc[0], a2r[0][3], B23.z, B23.w);
            mma16(acc[1], a2r[1][3], B23.z, B23.w);

            const int c = nt * 8 + 2 * q;
            const float2 bb = *(const float2*)(sB2 + c);
            const float2 ww = *(const float2*)(sW3s + c);
            s[0] += fmaxf(acc[0][0] + bb.x, 0.0f) * ww.x
                  + fmaxf(acc[0][1] + bb.y, 0.0f) * ww.y;
            s[1] += fmaxf(acc[0][2] + bb.x, 0.0f) * ww.x
                  + fmaxf(acc[0][3] + bb.y, 0.0f) * ww.y;
            s[2] += fmaxf(acc[1][0] + bb.x, 0.0f) * ww.x
                  + fmaxf(acc[1][1] + bb.y, 0.0f) * ww.y;
            s[3] += fmaxf(acc[1][2] + bb.x, 0.0f) * ww.x
                  + fmaxf(acc[1][3] + bb.y, 0.0f) * ww.y;
        }
#pragma unroll
        for (int i = 0; i < 4; i++) {
            s[i] += __shfl_xor_sync(0xFFFFFFFFu, s[i], 1);
            s[i] += __shfl_xor_sync(0xFFFFFFFFu, s[i], 2);
        }
        if (q == 0) {
#pragma unroll
            for (int i = 0; i < 4; i++) {
                float v = fminf(fmaxf(s[i] + sB3v, -15.0f), 15.0f);
                float e = __expf(2.0f * v);
                out[p0 + g + i * 8] = __fdividef(e - 1.0f, e + 1.0f);
            }
        }

#pragma unroll
        for (int r = 0; r < 4; r++) fcur[r] = fnext[r];
    }
}

// ---------------- Launch ----------------
extern "C" void kernel_launch(void* const* d_in, const int* in_sizes, int n_in,
                              void* d_out, int out_size)
{
    const float* points = (const float*)d_in[0];
    const float* grid   = (const float*)d_in[1];
    const float* W1     = (const float*)d_in[2];
    const float* b1     = (const float*)d_in[3];
    const float* W2     = (const float*)d_in[4];
    const float* b2     = (const float*)d_in[5];
    const float* W3     = (const float*)d_in[6];
    const float* b3     = (const float*)d_in[7];

    occ_mlp_kernel<<<NBLOCKS, CTA_THREADS>>>(points, grid, W1, b1, W2, b2, W3, b3,
                                             (float*)d_out);
}

// round 8
// speedup vs baseline: 1.2710x; 1.2710x over previous
#include <cuda_runtime.h>
#include <cuda_fp16.h>
#include <cstdint>

#define N_POINTS    2097152
#define CTA_THREADS 64
#define TILE_PTS    64                      // 2 warps x 32 rows
#define NTILES      (N_POINTS / TILE_PTS)   // 32768
#define NBLOCKS     (148 * 8)               // persistent

#define FEAT_STRIDE 24     // halves: 16 data + 8 pad, conflict-free
#define SCR_HALVES  (32 * FEAT_STRIDE)      // 768 halves = 1.5KB/warp

static __device__ __forceinline__ uint32_t pack_rn(float a, float b) {
    __half2 h = __floats2half2_rn(a, b);
    return *reinterpret_cast<uint32_t*>(&h);
}
static __device__ __forceinline__ __half2 u2h(uint32_t u) {
    return *reinterpret_cast<__half2*>(&u);
}
static __device__ __forceinline__ uint32_t h2u(__half2 h) {
    return *reinterpret_cast<uint32_t*>(&h);
}

// m16n8k16 fp16 MMA, fp32 accumulate in place
static __device__ __forceinline__ void mma16(float* d, const uint32_t* a,
                                             uint32_t b0, uint32_t b1)
{
    asm volatile(
        "mma.sync.aligned.m16n8k16.row.col.f32.f16.f16.f32 "
        "{%0,%1,%2,%3}, {%4,%5,%6,%7}, {%8,%9}, {%0,%1,%2,%3};"
        : "+f"(d[0]), "+f"(d[1]), "+f"(d[2]), "+f"(d[3])
        : "r"(a[0]), "r"(a[1]), "r"(a[2]), "r"(a[3]), "r"(b0), "r"(b1));
}

// m16n8k16 fp16 MMA, fp16 D, C = 0
static __device__ __forceinline__ void mma16_h(uint32_t* d, const uint32_t* a,
                                               uint32_t b0, uint32_t b1)
{
    asm volatile(
        "mma.sync.aligned.m16n8k16.row.col.f16.f16.f16.f16 "
        "{%0,%1}, {%2,%3,%4,%5}, {%6,%7}, {%8,%8};"
        : "=r"(d[0]), "=r"(d[1])
        : "r"(a[0]), "r"(a[1]), "r"(a[2]), "r"(a[3]), "r"(b0), "r"(b1), "r"(0u));
}

// issue cell gathers from ALREADY-RESIDENT coords (no load stall at the shfl)
static __device__ __forceinline__ void cell_gather(
    const float4* __restrict__ cellbase,
    float x, float y, float z, int g, int q, float4 f[4])
{
    const int ix = (int)rintf(fminf(fmaxf(x * 127.0f, 0.0f), 127.0f));
    const int iy = (int)rintf(fminf(fmaxf(y * 127.0f, 0.0f), 127.0f));
    const int iz = (int)rintf(fminf(fmaxf(z * 127.0f, 0.0f), 127.0f));
    const uint32_t ci = (uint32_t)(((ix << 7) + iy) << 7) + (uint32_t)iz;
#pragma unroll
    for (int r = 0; r < 4; r++) {
        const uint32_t cis = __shfl_sync(0xFFFFFFFFu, ci, r * 8 + g);
        f[r] = __ldg(cellbase + (size_t)cis * 4 + q);
    }
}

__global__ void __launch_bounds__(CTA_THREADS, 8)
occ_mlp_kernel(const float* __restrict__ points, const float* __restrict__ grid,
               const float* __restrict__ W1, const float* __restrict__ b1,
               const float* __restrict__ W2, const float* __restrict__ b2,
               const float* __restrict__ W3, const float* __restrict__ b3,
               float* __restrict__ out)
{
    // W2 B-fragments in SMEM: frag f=(kt*8+nt) -> [32 lanes] uint2
    __shared__ __align__(16) uint32_t sW2f[32 * 32 * 2];   // 8 KB
    __shared__ __align__(16) float sB2[64], sW3s[64];
    __shared__ float sB3v;
    __shared__ __align__(16) unsigned short sScr[2][SCR_HALVES];  // 3 KB

    const int tid  = threadIdx.x;
    const int wid  = tid >> 5;
    const int lane = tid & 31;
    const int g    = lane >> 2;   // 0..7
    const int q    = lane & 3;    // 0..3

    // ---- W1 B-fragments + layer-1 bias (half2) register-resident ----
    uint2 w1f[8];
    uint32_t b1h[8];
#pragma unroll
    for (int nt = 0; nt < 8; nt++) {
        const float* Wn = W1 + (nt * 8 + g) * 16;
        w1f[nt].x = pack_rn(Wn[2 * q],     Wn[2 * q + 1]);
        w1f[nt].y = pack_rn(Wn[2 * q + 8], Wn[2 * q + 9]);
        const int c = nt * 8 + 2 * q;
        b1h[nt] = pack_rn(b1[c], b1[c + 1]);
    }
    // ---- stage W2 fragments into SMEM ----
    for (int i = tid; i < 32 * 32 * 2; i += CTA_THREADS) {
        int f = i >> 6, ln = (i >> 1) & 31, r = i & 1;
        int kt = f >> 3, nt = f & 7;
        int n = nt * 8 + (ln >> 2);
        int k = kt * 16 + 2 * (ln & 3) + 8 * r;
        sW2f[i] = pack_rn(W2[n * 64 + k], W2[n * 64 + k + 1]);
    }
    if (tid < 64) { sB2[tid] = b2[tid]; sW3s[tid] = W3[tid]; }
    if (tid == 0) sB3v = b3[0];
    __syncthreads();

    unsigned short* scrF = sScr[wid];   // 32 rows x 24 halves
    const float4* cellbase = (const float4*)grid;
    const __half2 zero2 = __floats2half2_rn(0.0f, 0.0f);
    const int lbase = wid * 32 + lane;

    // ---- prologue: gather tile t (cold), prefetch coords for tile t+1 ----
    float4 fcur[4];
    float cx, cy, cz;
    {
        const int t0 = blockIdx.x;
        if (t0 < NTILES) {
            const int p = t0 * TILE_PTS + lbase;
            const float x0 = __ldg(points + 3 * p);
            const float y0 = __ldg(points + 3 * p + 1);
            const float z0 = __ldg(points + 3 * p + 2);
            cell_gather(cellbase, x0, y0, z0, g, q, fcur);
        }
        const int t1 = t0 + gridDim.x;
        if (t1 < NTILES) {
            const int p = t1 * TILE_PTS + lbase;
            cx = __ldg(points + 3 * p);
            cy = __ldg(points + 3 * p + 1);
            cz = __ldg(points + 3 * p + 2);
        }
    }

    for (int tile = blockIdx.x; tile < NTILES; tile += gridDim.x) {
        const int p0 = tile * TILE_PTS + wid * 32;

        // ---- commit current gather to SMEM (fp16) ----
#pragma unroll
        for (int r = 0; r < 4; r++) {
            const int pp = r * 8 + g;
            uint2 u;
            u.x = pack_rn(fcur[r].x, fcur[r].y);
            u.y = pack_rn(fcur[r].z, fcur[r].w);
            *(uint2*)(scrF + pp * FEAT_STRIDE + q * 4) = u;
        }

        // ---- issue NEXT tile's cell gathers (coords already resident) ----
        float4 fnext[4];
        const int ntile = tile + gridDim.x;
        if (ntile < NTILES)
            cell_gather(cellbase, cx, cy, cz, g, q, fnext);

        // ---- issue coords loads for tile t+2 (land by next iteration) ----
        const int nntile = tile + 2 * gridDim.x;
        if (nntile < NTILES) {
            const int p = nntile * TILE_PTS + lbase;
            cx = __ldg(points + 3 * p);
            cy = __ldg(points + 3 * p + 1);
            cz = __ldg(points + 3 * p + 2);
        }
        __syncwarp();

        // ---- layer-1 A-fragments ----
        uint32_t af[2][4];
#pragma unroll
        for (int rt = 0; rt < 2; rt++) {
            const unsigned short* A = scrF + (rt * 16 + g) * FEAT_STRIDE + 2 * q;
            af[rt][0] = *(const uint32_t*)(A);
            af[rt][1] = *(const uint32_t*)(A + 8 * FEAT_STRIDE);
            af[rt][2] = *(const uint32_t*)(A + 8);
            af[rt][3] = *(const uint32_t*)(A + 8 * FEAT_STRIDE + 8);
        }
        __syncwarp();   // af read done; scrF free for next-iter commit

        // ---- layer 1 (f16 D) -> layer-2 A-fragments ENTIRELY in registers ----
        uint32_t a2r[2][4][4];   // [rt][kt][areg]
#pragma unroll
        for (int nt = 0; nt < 8; nt++) {
            const int kt = nt >> 1, hi = (nt & 1) * 2;
#pragma unroll
            for (int rt = 0; rt < 2; rt++) {
                uint32_t d[2];
                mma16_h(d, af[rt], w1f[nt].x, w1f[nt].y);
                a2r[rt][kt][hi]     = h2u(__hmax2(__hadd2(u2h(d[0]), u2h(b1h[nt])), zero2));
                a2r[rt][kt][hi + 1] = h2u(__hmax2(__hadd2(u2h(d[1]), u2h(b1h[nt])), zero2));
            }
        }

        // ---- layer 2 + 3 fused ----
        float s[4] = {0.0f, 0.0f, 0.0f, 0.0f};   // rows g, g+8, g+16, g+24
#pragma unroll
        for (int nt = 0; nt < 8; nt++) {
            float acc[2][4];
            acc[0][0] = acc[0][1] = acc[0][2] = acc[0][3] = 0.0f;
            acc[1][0] = acc[1][1] = acc[1][2] = acc[1][3] = 0.0f;
#pragma unroll
            for (int kt = 0; kt < 4; kt++) {
                const uint2 b = *(const uint2*)(sW2f + ((kt * 8 + nt) * 32 + lane) * 2);
                mma16(acc[0], a2r[0][kt], b.x, b.y);
                mma16(acc[1], a2r[1][kt], b.x, b.y);
            }
            const int c = nt * 8 + 2 * q;
            const float2 bb = *(const float2*)(sB2 + c);
            const float2 ww = *(const float2*)(sW3s + c);
            s[0] += fmaxf(acc[0][0] + bb.x, 0.0f) * ww.x
                  + fmaxf(acc[0][1] + bb.y, 0.0f) * ww.y;
            s[1] += fmaxf(acc[0][2] + bb.x, 0.0f) * ww.x
                  + fmaxf(acc[0][3] + bb.y, 0.0f) * ww.y;
            s[2] += fmaxf(acc[1][0] + bb.x, 0.0f) * ww.x
                  + fmaxf(acc[1][1] + bb.y, 0.0f) * ww.y;
            s[3] += fmaxf(acc[1][2] + bb.x, 0.0f) * ww.x
                  + fmaxf(acc[1][3] + bb.y, 0.0f) * ww.y;
        }
#pragma unroll
        for (int i = 0; i < 4; i++) {
            s[i] += __shfl_xor_sync(0xFFFFFFFFu, s[i], 1);
            s[i] += __shfl_xor_sync(0xFFFFFFFFu, s[i], 2);
        }
        if (q == 0) {
#pragma unroll
            for (int i = 0; i < 4; i++) {
                float v = fminf(fmaxf(s[i] + sB3v, -15.0f), 15.0f);
                float e = __expf(2.0f * v);
                out[p0 + g + i * 8] = __fdividef(e - 1.0f, e + 1.0f);
            }
        }

#pragma unroll
        for (int r = 0; r < 4; r++) fcur[r] = fnext[r];
    }
}

// ---------------- Launch ----------------
extern "C" void kernel_launch(void* const* d_in, const int* in_sizes, int n_in,
                              void* d_out, int out_size)
{
    const float* points = (const float*)d_in[0];
    const float* grid   = (const float*)d_in[1];
    const float* W1     = (const float*)d_in[2];
    const float* b1     = (const float*)d_in[3];
    const float* W2     = (const float*)d_in[4];
    const float* b2     = (const float*)d_in[5];
    const float* W3     = (const float*)d_in[6];
    const float* b3     = (const float*)d_in[7];

    occ_mlp_kernel<<<NBLOCKS, CTA_THREADS>>>(points, grid, W1, b1, W2, b2, W3, b3,
                                             (float*)d_out);
}